// round 1
// baseline (speedup 1.0000x reference)
#include <cuda_runtime.h>

// QuantumLinear reduces algebraically to: out = x @ weight_real^T + bias
//   magnitude * cos(atan2(imag, real)) == real   (identically)
// so weight_imag is dead. Single fp32 NT-GEMM.
//
// M=8192, N=4096, K=4096 (all multiples of tile sizes; no bounds checks).

#define BM 128
#define BN 128
#define BK 16
#define TM 8
#define TN 8
#define NTHREADS 256   // (BM/TM)*(BN/TN)

__global__ __launch_bounds__(NTHREADS, 2)
void qlinear_sgemm(const float* __restrict__ X,   // [M, K] row-major
                   const float* __restrict__ W,   // [N, K] row-major
                   const float* __restrict__ bias,// [N]
                   float* __restrict__ Out,       // [M, N] row-major
                   int M, int N, int K)
{
    // Transposed-in-shared tiles: As[k][m], Bs[k][n] so the compute loop
    // reads contiguous float4 along m / n.
    __shared__ float As[BK][BM + 4];
    __shared__ float Bs[BK][BN + 4];

    const int bm = blockIdx.y * BM;
    const int bn = blockIdx.x * BN;
    const int tid = threadIdx.x;

    const int tx = tid & 15;   // 0..15 -> column group (TN*tx)
    const int ty = tid >> 4;   // 0..15 -> row group    (TM*ty)

    // Global-load mapping: each K-tile of A is BM x BK floats = 128*16
    //  = 512 float4; 256 threads -> 2 float4 each. Same for B.
    const int ld_row = tid >> 2;        // 0..63   (row within tile, +64 for 2nd)
    const int ld_c4  = tid & 3;         // 0..3    (which float4 along K)

    const float* Xg = X + (long long)(bm + ld_row) * K + ld_c4 * 4;
    const float* Wg = W + (long long)(bn + ld_row) * K + ld_c4 * 4;
    const long long half = (long long)64 * K;   // +64 rows

    float acc[TM][TN];
    #pragma unroll
    for (int i = 0; i < TM; i++)
        #pragma unroll
        for (int j = 0; j < TN; j++)
            acc[i][j] = 0.0f;

    for (int k0 = 0; k0 < K; k0 += BK) {
        // ---- load A tile (2 float4 per thread), store transposed ----
        float4 a0 = *(const float4*)(Xg + k0);
        float4 a1 = *(const float4*)(Xg + k0 + half);
        float4 b0 = *(const float4*)(Wg + k0);
        float4 b1 = *(const float4*)(Wg + k0 + half);

        {
            const int c = ld_c4 * 4;
            As[c + 0][ld_row] = a0.x;  As[c + 1][ld_row] = a0.y;
            As[c + 2][ld_row] = a0.z;  As[c + 3][ld_row] = a0.w;
            As[c + 0][ld_row + 64] = a1.x;  As[c + 1][ld_row + 64] = a1.y;
            As[c + 2][ld_row + 64] = a1.z;  As[c + 3][ld_row + 64] = a1.w;

            Bs[c + 0][ld_row] = b0.x;  Bs[c + 1][ld_row] = b0.y;
            Bs[c + 2][ld_row] = b0.z;  Bs[c + 3][ld_row] = b0.w;
            Bs[c + 0][ld_row + 64] = b1.x;  Bs[c + 1][ld_row + 64] = b1.y;
            Bs[c + 2][ld_row + 64] = b1.z;  Bs[c + 3][ld_row + 64] = b1.w;
        }
        __syncthreads();

        // ---- compute: 16 k-steps of 8x8 outer product ----
        #pragma unroll
        for (int k = 0; k < BK; k++) {
            float a[TM], b[TN];
            float4 av0 = *(const float4*)&As[k][ty * TM];
            float4 av1 = *(const float4*)&As[k][ty * TM + 4];
            float4 bv0 = *(const float4*)&Bs[k][tx * TN];
            float4 bv1 = *(const float4*)&Bs[k][tx * TN + 4];
            a[0]=av0.x; a[1]=av0.y; a[2]=av0.z; a[3]=av0.w;
            a[4]=av1.x; a[5]=av1.y; a[6]=av1.z; a[7]=av1.w;
            b[0]=bv0.x; b[1]=bv0.y; b[2]=bv0.z; b[3]=bv0.w;
            b[4]=bv1.x; b[5]=bv1.y; b[6]=bv1.z; b[7]=bv1.w;

            #pragma unroll
            for (int i = 0; i < TM; i++)
                #pragma unroll
                for (int j = 0; j < TN; j++)
                    acc[i][j] = fmaf(a[i], b[j], acc[i][j]);
        }
        __syncthreads();
    }

    // ---- epilogue: add bias, vectorized stores ----
    const int out_col = bn + tx * TN;
    float4 bias0 = *(const float4*)(bias + out_col);
    float4 bias1 = *(const float4*)(bias + out_col + 4);

    #pragma unroll
    for (int i = 0; i < TM; i++) {
        const int row = bm + ty * TM + i;
        float4 r0, r1;
        r0.x = acc[i][0] + bias0.x;  r0.y = acc[i][1] + bias0.y;
        r0.z = acc[i][2] + bias0.z;  r0.w = acc[i][3] + bias0.w;
        r1.x = acc[i][4] + bias1.x;  r1.y = acc[i][5] + bias1.y;
        r1.z = acc[i][6] + bias1.z;  r1.w = acc[i][7] + bias1.w;
        *(float4*)(Out + (long long)row * N + out_col)     = r0;
        *(float4*)(Out + (long long)row * N + out_col + 4) = r1;
    }
}

extern "C" void kernel_launch(void* const* d_in, const int* in_sizes, int n_in,
                              void* d_out, int out_size)
{
    const float* x    = (const float*)d_in[0];   // [M, K]
    const float* wr   = (const float*)d_in[1];   // [N, K]
    // d_in[2] = weight_imag: algebraically dead (magnitude*cos(phase) == real)
    const float* bias = (const float*)d_in[3];   // [N]
    float* out = (float*)d_out;

    const int N = in_sizes[3];            // 4096
    const int K = in_sizes[1] / N;        // 4096
    const int M = in_sizes[0] / K;        // 8192

    dim3 grid(N / BN, M / BM);            // (32, 64)
    qlinear_sgemm<<<grid, NTHREADS>>>(x, wr, bias, out, M, N, K);
}

// round 3
// speedup vs baseline: 2.2769x; 2.2769x over previous
#include <cuda_runtime.h>
#include <cuda_bf16.h>
#include <cstdint>

// QuantumLinear == x @ W_real^T + bias  (magnitude*cos(atan2(i,r)) == r identically;
// weight_imag is dead code).
//
// sm_103 harness compiles with BASE compute_103 PTX target -> no tcgen05/'a' ISA.
// Use base-ISA tensor cores: mma.sync.m16n8k16 bf16 (fallback HMMA) + cp.async.
//
// Precision: fp32 -> bf16 hi/lo split on both operands, 3 accumulation passes
//   out = xh@wh^T + xh@wl^T + xl@wh^T   (lo*lo dropped, ~2^-18 relative)

#define M_DIM 8192
#define N_DIM 4096
#define K_DIM 4096

#define BM 128
#define BN 128
#define BK 32
#define STAGES 4
#define KTILES (K_DIM / BK)       // 128 per pass
#define NPASS 3
#define TOTAL_STAGES (KTILES * NPASS)  // 384

// smem: padded rows, 80B stride (64B data + 16B pad) -> conflict-free ldmatrix
#define ROW_STRIDE 80
#define TILE_BYTES (128 * ROW_STRIDE)          // 10240
#define STAGE_BYTES (2 * TILE_BYTES)           // A + B = 20480
#define SMEM_TOTAL (STAGES * STAGE_BYTES)      // 81920

// ---------------- scratch ----------------
__device__ __nv_bfloat16 g_xhi[(size_t)M_DIM * K_DIM];
__device__ __nv_bfloat16 g_xlo[(size_t)M_DIM * K_DIM];
__device__ __nv_bfloat16 g_whi[(size_t)N_DIM * K_DIM];
__device__ __nv_bfloat16 g_wlo[(size_t)N_DIM * K_DIM];

// ---------------- helpers ----------------
__device__ __forceinline__ uint32_t smem_u32(const void* p) {
    uint32_t a;
    asm("{ .reg .u64 t; cvta.to.shared.u64 t, %1; cvt.u32.u64 %0, t; }" : "=r"(a) : "l"(p));
    return a;
}

__device__ __forceinline__ void cp16(uint32_t dst, const void* src) {
    asm volatile("cp.async.cg.shared.global [%0], [%1], 16;" :: "r"(dst), "l"(src));
}
#define CP_COMMIT() asm volatile("cp.async.commit_group;" ::: "memory")
#define CP_WAIT(n)  asm volatile("cp.async.wait_group %0;" :: "n"(n) : "memory")

__device__ __forceinline__ void ldsm4(uint32_t* r, uint32_t addr) {
    asm volatile("ldmatrix.sync.aligned.m8n8.x4.shared.b16 {%0,%1,%2,%3}, [%4];"
                 : "=r"(r[0]), "=r"(r[1]), "=r"(r[2]), "=r"(r[3]) : "r"(addr));
}

__device__ __forceinline__ void mma16816(float* d, const uint32_t* a,
                                         uint32_t b0, uint32_t b1) {
    asm volatile(
        "mma.sync.aligned.m16n8k16.row.col.f32.bf16.bf16.f32 "
        "{%0,%1,%2,%3}, {%4,%5,%6,%7}, {%8,%9}, {%0,%1,%2,%3};"
        : "+f"(d[0]), "+f"(d[1]), "+f"(d[2]), "+f"(d[3])
        : "r"(a[0]), "r"(a[1]), "r"(a[2]), "r"(a[3]), "r"(b0), "r"(b1));
}

// ---------------- split kernel: fp32 -> bf16 hi + bf16 lo ----------------
__global__ __launch_bounds__(256)
void split_bf16(const float4* __restrict__ src,
                __nv_bfloat162* __restrict__ hi,
                __nv_bfloat162* __restrict__ lo, int n4)
{
    int i = blockIdx.x * blockDim.x + threadIdx.x;
    if (i >= n4) return;
    float4 v = src[i];
    __nv_bfloat16 h0 = __float2bfloat16(v.x);
    __nv_bfloat16 h1 = __float2bfloat16(v.y);
    __nv_bfloat16 h2 = __float2bfloat16(v.z);
    __nv_bfloat16 h3 = __float2bfloat16(v.w);
    __nv_bfloat16 l0 = __float2bfloat16(v.x - __bfloat162float(h0));
    __nv_bfloat16 l1 = __float2bfloat16(v.y - __bfloat162float(h1));
    __nv_bfloat16 l2 = __float2bfloat16(v.z - __bfloat162float(h2));
    __nv_bfloat16 l3 = __float2bfloat16(v.w - __bfloat162float(h3));
    hi[2 * i]     = __nv_bfloat162(h0, h1);
    hi[2 * i + 1] = __nv_bfloat162(h2, h3);
    lo[2 * i]     = __nv_bfloat162(l0, l1);
    lo[2 * i + 1] = __nv_bfloat162(l2, l3);
}

// ---------------- GEMM ----------------
__global__ __launch_bounds__(256, 2)
void qgemm_hmma(const __nv_bfloat16* __restrict__ xh,
                const __nv_bfloat16* __restrict__ xl,
                const __nv_bfloat16* __restrict__ wh,
                const __nv_bfloat16* __restrict__ wl,
                const float* __restrict__ bias,
                float* __restrict__ out)
{
    extern __shared__ char smem[];
    const uint32_t sb = smem_u32(smem);

    const int tid  = threadIdx.x;
    const int wid  = tid >> 5;
    const int lane = tid & 31;
    const int warpM = wid & 3;      // 0..3 -> m offset 32*warpM
    const int warpN = wid >> 2;     // 0..1 -> n offset 64*warpN

    // ---- grouped rasterization: 8 m-tiles per group column ----
    const int pid = blockIdx.x;
    const int group_id = pid >> 8;              // / (8 * 32)
    const int first_m  = group_id << 3;
    const int pid_m = first_m + (pid & 7);      // group_size_m == 8 always (64 % 8 == 0)
    const int pid_n = (pid & 255) >> 3;
    const int bm = pid_m * BM;
    const int bn = pid_n * BN;

    // ---- global load mapping: 2 rows per thread per tile, 16B chunks ----
    const int ldr   = tid >> 2;       // 0..63
    const int chunk = tid & 3;        // 0..3 (16B = 8 bf16)
    const size_t aOff0 = (size_t)(bm + ldr) * K_DIM + chunk * 8;
    const size_t aOff1 = aOff0 + (size_t)64 * K_DIM;
    const size_t bOff0 = (size_t)(bn + ldr) * K_DIM + chunk * 8;
    const size_t bOff1 = bOff0 + (size_t)64 * K_DIM;
    const uint32_t sA0 = ldr * ROW_STRIDE + chunk * 16;
    const uint32_t sA1 = sA0 + 64 * ROW_STRIDE;
    // B tile sits at +TILE_BYTES within a stage

    const __nv_bfloat16* pAs[NPASS] = {xh, xh, xl};
    const __nv_bfloat16* pBs[NPASS] = {wh, wl, wh};

    // ---- ldmatrix lane address bases ----
    const uint32_t aLane = sb +
        (uint32_t)((warpM * 32 + (lane & 15)) * ROW_STRIDE + ((lane >> 4) * 16));
    const uint32_t bLane = sb + TILE_BYTES +
        (uint32_t)((warpN * 64 + (lane & 7) + ((lane & 16) >> 1)) * ROW_STRIDE +
                   (((lane >> 3) & 1) * 16));

    float acc[2][8][4];
    #pragma unroll
    for (int i = 0; i < 2; i++)
        #pragma unroll
        for (int j = 0; j < 8; j++)
            #pragma unroll
            for (int q = 0; q < 4; q++)
                acc[i][j][q] = 0.0f;

    // ---- prologue: issue stages 0..STAGES-2 ----
    #pragma unroll
    for (int s = 0; s < STAGES - 1; s++) {
        const __nv_bfloat16* pA = pAs[s >> 7];
        const __nv_bfloat16* pB = pBs[s >> 7];
        const int k0 = (s & (KTILES - 1)) * BK;
        const uint32_t st = sb + s * STAGE_BYTES;
        cp16(st + sA0, pA + aOff0 + k0);
        cp16(st + sA1, pA + aOff1 + k0);
        cp16(st + TILE_BYTES + sA0, pB + bOff0 + k0);
        cp16(st + TILE_BYTES + sA1, pB + bOff1 + k0);
        CP_COMMIT();
    }

    // ---- main loop ----
    #pragma unroll 1
    for (int s = 0; s < TOTAL_STAGES; s++) {
        CP_WAIT(STAGES - 2);
        __syncthreads();

        // issue load for stage s + STAGES-1 into buffer (s-1) % STAGES
        const int ls = s + STAGES - 1;
        if (ls < TOTAL_STAGES) {
            const __nv_bfloat16* pA = pAs[ls >> 7];
            const __nv_bfloat16* pB = pBs[ls >> 7];
            const int k0 = (ls & (KTILES - 1)) * BK;
            const uint32_t st = sb + (ls & (STAGES - 1)) * STAGE_BYTES;
            cp16(st + sA0, pA + aOff0 + k0);
            cp16(st + sA1, pA + aOff1 + k0);
            cp16(st + TILE_BYTES + sA0, pB + bOff0 + k0);
            cp16(st + TILE_BYTES + sA1, pB + bOff1 + k0);
        }
        CP_COMMIT();

        // compute on buffer s % STAGES
        const uint32_t stOff = (uint32_t)((s & (STAGES - 1)) * STAGE_BYTES);
        #pragma unroll
        for (int ks = 0; ks < 2; ks++) {
            uint32_t ar[2][4], br[4][4];
            ldsm4(ar[0], aLane + stOff + ks * 32);
            ldsm4(ar[1], aLane + stOff + ks * 32 + 16 * ROW_STRIDE);
            #pragma unroll
            for (int nt2 = 0; nt2 < 4; nt2++)
                ldsm4(br[nt2], bLane + stOff + ks * 32 + nt2 * (16 * ROW_STRIDE));
            #pragma unroll
            for (int mt = 0; mt < 2; mt++)
                #pragma unroll
                for (int nt = 0; nt < 8; nt++)
                    mma16816(acc[mt][nt], ar[mt],
                             br[nt >> 1][(nt & 1) * 2], br[nt >> 1][(nt & 1) * 2 + 1]);
        }
    }

    // ---- epilogue: direct stores + bias ----
    const int g = lane >> 2;
    const int t = lane & 3;
    #pragma unroll
    for (int mt = 0; mt < 2; mt++) {
        const int row0 = bm + warpM * 32 + mt * 16 + g;
        #pragma unroll
        for (int nt = 0; nt < 8; nt++) {
            const int col = bn + warpN * 64 + nt * 8 + 2 * t;
            const float2 b2 = *(const float2*)(bias + col);
            float2 o0, o1;
            o0.x = acc[mt][nt][0] + b2.x;
            o0.y = acc[mt][nt][1] + b2.y;
            o1.x = acc[mt][nt][2] + b2.x;
            o1.y = acc[mt][nt][3] + b2.y;
            *(float2*)(out + (size_t)row0 * N_DIM + col)       = o0;
            *(float2*)(out + (size_t)(row0 + 8) * N_DIM + col) = o1;
        }
    }
}

// ---------------- host ----------------
extern "C" void kernel_launch(void* const* d_in, const int* in_sizes, int n_in,
                              void* d_out, int out_size)
{
    const float* x    = (const float*)d_in[0];   // [M, K]
    const float* wr   = (const float*)d_in[1];   // [N, K]
    // d_in[2] = weight_imag: algebraically dead
    const float* bias = (const float*)d_in[3];   // [N]
    float* out = (float*)d_out;

    void *p_xhi, *p_xlo, *p_whi, *p_wlo;
    cudaGetSymbolAddress(&p_xhi, g_xhi);
    cudaGetSymbolAddress(&p_xlo, g_xlo);
    cudaGetSymbolAddress(&p_whi, g_whi);
    cudaGetSymbolAddress(&p_wlo, g_wlo);

    {
        int n4x = M_DIM * K_DIM / 4;
        int n4w = N_DIM * K_DIM / 4;
        split_bf16<<<n4x / 256, 256>>>((const float4*)x, (__nv_bfloat162*)p_xhi,
                                       (__nv_bfloat162*)p_xlo, n4x);
        split_bf16<<<n4w / 256, 256>>>((const float4*)wr, (__nv_bfloat162*)p_whi,
                                       (__nv_bfloat162*)p_wlo, n4w);
    }

    cudaFuncSetAttribute(qgemm_hmma, cudaFuncAttributeMaxDynamicSharedMemorySize,
                         SMEM_TOTAL);

    const int nblocks = (M_DIM / BM) * (N_DIM / BN);   // 2048
    qgemm_hmma<<<nblocks, 256, SMEM_TOTAL>>>(
        (const __nv_bfloat16*)p_xhi, (const __nv_bfloat16*)p_xlo,
        (const __nv_bfloat16*)p_whi, (const __nv_bfloat16*)p_wlo,
        bias, out);
}

// round 4
// speedup vs baseline: 2.4250x; 1.0650x over previous
#include <cuda_runtime.h>
#include <cuda_bf16.h>
#include <cstdint>

// QuantumLinear == x @ W_real^T + bias  (magnitude*cos(atan2(i,r)) == r identically;
// weight_imag is dead code).
//
// Round 4: single-pass TF32 mma.m16n8k8 (base ISA; fallback HMMA is paced
// per-instruction, so 134M tf32 instrs beat 201M bf16 instrs).
// Inputs loaded as raw fp32; fragments rounded in-register with cvt.rna.tf32.f32
// (round-to-nearest: unbiased, ~1.5e-4 rel err; truncation would bias ~1e-3).

#define M_DIM 8192
#define N_DIM 4096
#define K_DIM 4096

#define BM 128
#define BN 128
#define BK 32                       // fp32 elements per K-tile (128B rows)
#define STAGES 3
#define KTILES (K_DIM / BK)         // 128

// smem rows padded: 128B data + 16B pad = 144B (9*16B, odd -> conflict-free ldsm)
#define ROW_STRIDE 144
#define TILE_BYTES (128 * ROW_STRIDE)          // 18432
#define STAGE_BYTES (2 * TILE_BYTES)           // 36864
#define SMEM_TOTAL (STAGES * STAGE_BYTES)      // 110592

// ---------------- helpers ----------------
__device__ __forceinline__ uint32_t smem_u32(const void* p) {
    uint32_t a;
    asm("{ .reg .u64 t; cvta.to.shared.u64 t, %1; cvt.u32.u64 %0, t; }" : "=r"(a) : "l"(p));
    return a;
}

__device__ __forceinline__ void cp16(uint32_t dst, const void* src) {
    asm volatile("cp.async.cg.shared.global [%0], [%1], 16;" :: "r"(dst), "l"(src));
}
#define CP_COMMIT() asm volatile("cp.async.commit_group;" ::: "memory")
#define CP_WAIT(n)  asm volatile("cp.async.wait_group %0;" :: "n"(n) : "memory")

__device__ __forceinline__ void ldsm4(uint32_t* r, uint32_t addr) {
    asm volatile("ldmatrix.sync.aligned.m8n8.x4.shared.b16 {%0,%1,%2,%3}, [%4];"
                 : "=r"(r[0]), "=r"(r[1]), "=r"(r[2]), "=r"(r[3]) : "r"(addr));
}

__device__ __forceinline__ void cvt4(uint32_t* r) {
    asm volatile("cvt.rna.tf32.f32 %0, %0;" : "+r"(r[0]));
    asm volatile("cvt.rna.tf32.f32 %0, %0;" : "+r"(r[1]));
    asm volatile("cvt.rna.tf32.f32 %0, %0;" : "+r"(r[2]));
    asm volatile("cvt.rna.tf32.f32 %0, %0;" : "+r"(r[3]));
}

__device__ __forceinline__ void mma1688(float* d, const uint32_t* a,
                                        uint32_t b0, uint32_t b1) {
    asm volatile(
        "mma.sync.aligned.m16n8k8.row.col.f32.tf32.tf32.f32 "
        "{%0,%1,%2,%3}, {%4,%5,%6,%7}, {%8,%9}, {%0,%1,%2,%3};"
        : "+f"(d[0]), "+f"(d[1]), "+f"(d[2]), "+f"(d[3])
        : "r"(a[0]), "r"(a[1]), "r"(a[2]), "r"(a[3]), "r"(b0), "r"(b1));
}

// ---------------- GEMM ----------------
__global__ __launch_bounds__(256, 2)
void qgemm_tf32(const float* __restrict__ X,    // [M, K]
                const float* __restrict__ W,    // [N, K]
                const float* __restrict__ bias, // [N]
                float* __restrict__ out)        // [M, N]
{
    extern __shared__ char smem[];
    const uint32_t sb = smem_u32(smem);

    const int tid  = threadIdx.x;
    const int wid  = tid >> 5;
    const int lane = tid & 31;
    const int warpM = wid & 3;      // m offset 32*warpM
    const int warpN = wid >> 2;     // n offset 64*warpN

    // ---- grouped rasterization: 8 m-tiles per group column ----
    const int pid = blockIdx.x;
    const int group_id = pid >> 8;
    const int pid_m = (group_id << 3) + (pid & 7);
    const int pid_n = (pid & 255) >> 3;
    const int bm = pid_m * BM;
    const int bn = pid_n * BN;

    // ---- global load mapping: 1 row per thread, 4x16B chunks per tile ----
    const int r = tid >> 1;          // 0..127 (row within tile)
    const int h = tid & 1;           // which 64B half of the 128B row
    const size_t aOff = (size_t)(bm + r) * K_DIM + h * 16;  // fp32 col offset
    const size_t bOff = (size_t)(bn + r) * K_DIM + h * 16;
    const uint32_t sRow = (uint32_t)(r * ROW_STRIDE + h * 64);

    // ---- ldmatrix lane bases (m8n8.x4 quadrants == tf32 fragment layout) ----
    const uint32_t aLane = sb +
        (uint32_t)((warpM * 32 + (lane & 15)) * ROW_STRIDE + ((lane >> 4) * 16));
    const uint32_t bLane = sb + TILE_BYTES +
        (uint32_t)((warpN * 64 + (lane & 7) + ((lane & 16) >> 1)) * ROW_STRIDE +
                   (((lane >> 3) & 1) * 16));

    float acc[2][8][4];
    #pragma unroll
    for (int i = 0; i < 2; i++)
        #pragma unroll
        for (int j = 0; j < 8; j++)
            #pragma unroll
            for (int q = 0; q < 4; q++)
                acc[i][j][q] = 0.0f;

    // ---- prologue: issue stages 0..STAGES-2 ----
    #pragma unroll
    for (int s = 0; s < STAGES - 1; s++) {
        const int k0 = s * BK;
        const uint32_t st = sb + s * STAGE_BYTES;
        #pragma unroll
        for (int c = 0; c < 4; c++) {
            cp16(st + sRow + c * 16, X + aOff + k0 + c * 4);
            cp16(st + TILE_BYTES + sRow + c * 16, W + bOff + k0 + c * 4);
        }
        CP_COMMIT();
    }

    uint32_t bufC = 0;                              // compute buffer offset
    uint32_t bufL = (STAGES - 1) * STAGE_BYTES;     // load buffer offset

    // ---- main loop ----
    #pragma unroll 1
    for (int s = 0; s < KTILES; s++) {
        CP_WAIT(STAGES - 2);
        __syncthreads();

        const int ls = s + STAGES - 1;
        if (ls < KTILES) {
            const int k0 = ls * BK;
            const uint32_t st = sb + bufL;
            #pragma unroll
            for (int c = 0; c < 4; c++) {
                cp16(st + sRow + c * 16, X + aOff + k0 + c * 4);
                cp16(st + TILE_BYTES + sRow + c * 16, W + bOff + k0 + c * 4);
            }
        }
        CP_COMMIT();

        // compute on bufC: 4 k8-slices
        #pragma unroll
        for (int ks = 0; ks < 4; ks++) {
            uint32_t ar[2][4], br[4][4];
            ldsm4(ar[0], aLane + bufC + ks * 32);
            ldsm4(ar[1], aLane + bufC + ks * 32 + 16 * ROW_STRIDE);
            cvt4(ar[0]);
            cvt4(ar[1]);
            #pragma unroll
            for (int p = 0; p < 4; p++) {
                ldsm4(br[p], bLane + bufC + ks * 32 + p * (16 * ROW_STRIDE));
                cvt4(br[p]);
            }
            #pragma unroll
            for (int mt = 0; mt < 2; mt++)
                #pragma unroll
                for (int nt = 0; nt < 8; nt++)
                    mma1688(acc[mt][nt], ar[mt],
                            br[nt >> 1][(nt & 1) * 2], br[nt >> 1][(nt & 1) * 2 + 1]);
        }

        bufC += STAGE_BYTES; if (bufC == SMEM_TOTAL) bufC = 0;
        bufL += STAGE_BYTES; if (bufL == SMEM_TOTAL) bufL = 0;
    }

    // ---- epilogue: direct stores + bias ----
    const int g = lane >> 2;
    const int t = lane & 3;
    #pragma unroll
    for (int mt = 0; mt < 2; mt++) {
        const int row0 = bm + warpM * 32 + mt * 16 + g;
        #pragma unroll
        for (int nt = 0; nt < 8; nt++) {
            const int col = bn + warpN * 64 + nt * 8 + 2 * t;
            const float2 b2 = *(const float2*)(bias + col);
            float2 o0, o1;
            o0.x = acc[mt][nt][0] + b2.x;
            o0.y = acc[mt][nt][1] + b2.y;
            o1.x = acc[mt][nt][2] + b2.x;
            o1.y = acc[mt][nt][3] + b2.y;
            *(float2*)(out + (size_t)row0 * N_DIM + col)       = o0;
            *(float2*)(out + (size_t)(row0 + 8) * N_DIM + col) = o1;
        }
    }
}

// ---------------- host ----------------
extern "C" void kernel_launch(void* const* d_in, const int* in_sizes, int n_in,
                              void* d_out, int out_size)
{
    const float* x    = (const float*)d_in[0];   // [M, K]
    const float* wr   = (const float*)d_in[1];   // [N, K]
    // d_in[2] = weight_imag: algebraically dead
    const float* bias = (const float*)d_in[3];   // [N]
    float* out = (float*)d_out;

    cudaFuncSetAttribute(qgemm_tf32, cudaFuncAttributeMaxDynamicSharedMemorySize,
                         SMEM_TOTAL);

    const int nblocks = (M_DIM / BM) * (N_DIM / BN);   // 2048
    qgemm_tf32<<<nblocks, 256, SMEM_TOTAL>>>(x, wr, bias, out);
}

// round 5
// speedup vs baseline: 2.7700x; 1.1423x over previous
#include <cuda_runtime.h>
#include <cstdint>

// QuantumLinear == x @ W_real^T + bias  (magnitude*cos(atan2(i,r)) == r identically;
// weight_imag is dead code).
//
// Round 5: tf32 mma.m16n8k8, inputs PRE-ROUNDED to tf32 (cvt.rna) in a prep pass
// so the GEMM loop is pure ldmatrix+mma, plus double-buffered register fragments
// to hide LDSM latency under the MMA stream.

#define M_DIM 8192
#define N_DIM 4096
#define K_DIM 4096

#define BM 128
#define BN 128
#define BK 32                       // fp32 elements per K-tile (128B rows)
#define STAGES 3
#define KTILES (K_DIM / BK)         // 128

// smem rows padded: 128B data + 16B pad = 144B (9*16B, odd -> conflict-free ldsm)
#define ROW_STRIDE 144
#define TILE_BYTES (128 * ROW_STRIDE)          // 18432
#define STAGE_BYTES (2 * TILE_BYTES)           // 36864
#define SMEM_TOTAL (STAGES * STAGE_BYTES)      // 110592

// ---------------- scratch: tf32-rounded copies ----------------
__device__ float g_xr[(size_t)M_DIM * K_DIM];
__device__ float g_wr[(size_t)N_DIM * K_DIM];

// ---------------- helpers ----------------
__device__ __forceinline__ uint32_t smem_u32(const void* p) {
    uint32_t a;
    asm("{ .reg .u64 t; cvta.to.shared.u64 t, %1; cvt.u32.u64 %0, t; }" : "=r"(a) : "l"(p));
    return a;
}

__device__ __forceinline__ void cp16(uint32_t dst, const void* src) {
    asm volatile("cp.async.cg.shared.global [%0], [%1], 16;" :: "r"(dst), "l"(src));
}
#define CP_COMMIT() asm volatile("cp.async.commit_group;" ::: "memory")
#define CP_WAIT(n)  asm volatile("cp.async.wait_group %0;" :: "n"(n) : "memory")

__device__ __forceinline__ void ldsm4(uint32_t* r, uint32_t addr) {
    asm volatile("ldmatrix.sync.aligned.m8n8.x4.shared.b16 {%0,%1,%2,%3}, [%4];"
                 : "=r"(r[0]), "=r"(r[1]), "=r"(r[2]), "=r"(r[3]) : "r"(addr));
}

__device__ __forceinline__ void mma1688(float* d, const uint32_t* a,
                                        uint32_t b0, uint32_t b1) {
    asm volatile(
        "mma.sync.aligned.m16n8k8.row.col.f32.tf32.tf32.f32 "
        "{%0,%1,%2,%3}, {%4,%5,%6,%7}, {%8,%9}, {%0,%1,%2,%3};"
        : "+f"(d[0]), "+f"(d[1]), "+f"(d[2]), "+f"(d[3])
        : "r"(a[0]), "r"(a[1]), "r"(a[2]), "r"(a[3]), "r"(b0), "r"(b1));
}

// ---------------- prep: fp32 -> tf32-exact fp32 (round-to-nearest) ----------------
__global__ __launch_bounds__(256)
void round_tf32(const uint4* __restrict__ src, uint4* __restrict__ dst, int n4)
{
    int i = blockIdx.x * blockDim.x + threadIdx.x;
    if (i >= n4) return;
    uint4 v = src[i];
    asm("cvt.rna.tf32.f32 %0, %0;" : "+r"(v.x));
    asm("cvt.rna.tf32.f32 %0, %0;" : "+r"(v.y));
    asm("cvt.rna.tf32.f32 %0, %0;" : "+r"(v.z));
    asm("cvt.rna.tf32.f32 %0, %0;" : "+r"(v.w));
    dst[i] = v;
}

// ---------------- GEMM ----------------
__global__ __launch_bounds__(256, 2)
void qgemm_tf32(const float* __restrict__ X,    // [M, K] tf32-exact
                const float* __restrict__ W,    // [N, K] tf32-exact
                const float* __restrict__ bias, // [N]
                float* __restrict__ out)        // [M, N]
{
    extern __shared__ char smem[];
    const uint32_t sb = smem_u32(smem);

    const int tid  = threadIdx.x;
    const int wid  = tid >> 5;
    const int lane = tid & 31;
    const int warpM = wid & 3;      // m offset 32*warpM
    const int warpN = wid >> 2;     // n offset 64*warpN

    // ---- grouped rasterization: 8 m-tiles per group column ----
    const int pid = blockIdx.x;
    const int group_id = pid >> 8;
    const int pid_m = (group_id << 3) + (pid & 7);
    const int pid_n = (pid & 255) >> 3;
    const int bm = pid_m * BM;
    const int bn = pid_n * BN;

    // ---- global load mapping: 1 row per thread, 4x16B chunks per tile ----
    const int r = tid >> 1;
    const int h = tid & 1;
    const size_t aOff = (size_t)(bm + r) * K_DIM + h * 16;
    const size_t bOff = (size_t)(bn + r) * K_DIM + h * 16;
    const uint32_t sRow = (uint32_t)(r * ROW_STRIDE + h * 64);

    // ---- ldmatrix lane bases ----
    const uint32_t aLane = sb +
        (uint32_t)((warpM * 32 + (lane & 15)) * ROW_STRIDE + ((lane >> 4) * 16));
    const uint32_t bLane = sb + TILE_BYTES +
        (uint32_t)((warpN * 64 + (lane & 7) + ((lane & 16) >> 1)) * ROW_STRIDE +
                   (((lane >> 3) & 1) * 16));

    float acc[2][8][4];
    #pragma unroll
    for (int i = 0; i < 2; i++)
        #pragma unroll
        for (int j = 0; j < 8; j++)
            #pragma unroll
            for (int q = 0; q < 4; q++)
                acc[i][j][q] = 0.0f;

    // ---- prologue ----
    #pragma unroll
    for (int s = 0; s < STAGES - 1; s++) {
        const int k0 = s * BK;
        const uint32_t st = sb + s * STAGE_BYTES;
        #pragma unroll
        for (int c = 0; c < 4; c++) {
            cp16(st + sRow + c * 16, X + aOff + k0 + c * 4);
            cp16(st + TILE_BYTES + sRow + c * 16, W + bOff + k0 + c * 4);
        }
        CP_COMMIT();
    }

    uint32_t bufC = 0;
    uint32_t bufL = (STAGES - 1) * STAGE_BYTES;

    // double-buffered fragments
    uint32_t ar[2][2][4];   // [buf][mt][reg]
    uint32_t br[2][4][4];   // [buf][npair][reg]

    // ---- main loop ----
    #pragma unroll 1
    for (int s = 0; s < KTILES; s++) {
        CP_WAIT(STAGES - 2);
        __syncthreads();

        const int ls = s + STAGES - 1;
        if (ls < KTILES) {
            const int k0 = ls * BK;
            const uint32_t st = sb + bufL;
            #pragma unroll
            for (int c = 0; c < 4; c++) {
                cp16(st + sRow + c * 16, X + aOff + k0 + c * 4);
                cp16(st + TILE_BYTES + sRow + c * 16, W + bOff + k0 + c * 4);
            }
        }
        CP_COMMIT();

        // load fragments for slice 0
        ldsm4(ar[0][0], aLane + bufC);
        ldsm4(ar[0][1], aLane + bufC + 16 * ROW_STRIDE);
        #pragma unroll
        for (int p = 0; p < 4; p++)
            ldsm4(br[0][p], bLane + bufC + p * (16 * ROW_STRIDE));

        #pragma unroll
        for (int ks = 0; ks < 4; ks++) {
            const int cur = ks & 1;
            const int nxt = cur ^ 1;
            if (ks < 3) {   // prefetch slice ks+1 while computing ks
                const uint32_t o = bufC + (ks + 1) * 32;
                ldsm4(ar[nxt][0], aLane + o);
                ldsm4(ar[nxt][1], aLane + o + 16 * ROW_STRIDE);
                #pragma unroll
                for (int p = 0; p < 4; p++)
                    ldsm4(br[nxt][p], bLane + o + p * (16 * ROW_STRIDE));
            }
            #pragma unroll
            for (int mt = 0; mt < 2; mt++)
                #pragma unroll
                for (int nt = 0; nt < 8; nt++)
                    mma1688(acc[mt][nt], ar[cur][mt],
                            br[cur][nt >> 1][(nt & 1) * 2],
                            br[cur][nt >> 1][(nt & 1) * 2 + 1]);
        }

        bufC += STAGE_BYTES; if (bufC == SMEM_TOTAL) bufC = 0;
        bufL += STAGE_BYTES; if (bufL == SMEM_TOTAL) bufL = 0;
    }

    // ---- epilogue ----
    const int g = lane >> 2;
    const int t = lane & 3;
    #pragma unroll
    for (int mt = 0; mt < 2; mt++) {
        const int row0 = bm + warpM * 32 + mt * 16 + g;
        #pragma unroll
        for (int nt = 0; nt < 8; nt++) {
            const int col = bn + warpN * 64 + nt * 8 + 2 * t;
            const float2 b2 = *(const float2*)(bias + col);
            float2 o0, o1;
            o0.x = acc[mt][nt][0] + b2.x;
            o0.y = acc[mt][nt][1] + b2.y;
            o1.x = acc[mt][nt][2] + b2.x;
            o1.y = acc[mt][nt][3] + b2.y;
            *(float2*)(out + (size_t)row0 * N_DIM + col)       = o0;
            *(float2*)(out + (size_t)(row0 + 8) * N_DIM + col) = o1;
        }
    }
}

// ---------------- host ----------------
extern "C" void kernel_launch(void* const* d_in, const int* in_sizes, int n_in,
                              void* d_out, int out_size)
{
    const float* x    = (const float*)d_in[0];   // [M, K]
    const float* wr   = (const float*)d_in[1];   // [N, K]
    // d_in[2] = weight_imag: algebraically dead
    const float* bias = (const float*)d_in[3];   // [N]
    float* out = (float*)d_out;

    void *p_xr, *p_wr;
    cudaGetSymbolAddress(&p_xr, g_xr);
    cudaGetSymbolAddress(&p_wr, g_wr);

    {
        int n4x = M_DIM * K_DIM / 4;
        int n4w = N_DIM * K_DIM / 4;
        round_tf32<<<n4x / 256, 256>>>((const uint4*)x, (uint4*)p_xr, n4x);
        round_tf32<<<n4w / 256, 256>>>((const uint4*)wr, (uint4*)p_wr, n4w);
    }

    cudaFuncSetAttribute(qgemm_tf32, cudaFuncAttributeMaxDynamicSharedMemorySize,
                         SMEM_TOTAL);

    const int nblocks = (M_DIM / BM) * (N_DIM / BN);   // 2048
    qgemm_tf32<<<nblocks, 256, SMEM_TOTAL>>>(
        (const float*)p_xr, (const float*)p_wr, bias, out);
}